// round 11
// baseline (speedup 1.0000x reference)
#include <cuda_runtime.h>
#include <cuda_fp16.h>
#include <cstdint>
#include <math.h>

#define NN   50000
#define EE   1600000
#define KDIM 1433
#define KP2  1440        // 45 * 32
#define NC   7
#define NITER 45

// ---------------- scratch (device globals; no allocs allowed) ----------------
__device__ __half g_yh[(size_t)NN * 64]; // x @ W_gcn [N,64] fp16 (scaled in-place by dis)
__device__ int   g_deg[NN];
__device__ float g_dis[NN];
__device__ int   g_rowptr[NN + 1];
__device__ int   g_cursor[NN];
__device__ int   g_csr[EE];
__device__ int   g_bsum[256];
__device__ int   g_boff[256];
__device__ __half g_Wh[96 * KP2];        // n-major fp16 of [Wg|Wps]

// ---------------- stream/event fork (created once at load; host objects) ------
static cudaStream_t g_s2;
static cudaEvent_t  g_ev0, g_ev1;
namespace {
struct _StrInit {
    _StrInit() {
        cudaStreamCreateWithFlags(&g_s2, cudaStreamNonBlocking);
        cudaEventCreateWithFlags(&g_ev0, cudaEventDisableTiming);
        cudaEventCreateWithFlags(&g_ev1, cudaEventDisableTiming);
    }
};
_StrInit _str_init;
}

// ---------------- degree / CSR build ----------------
__global__ void k_zero_deg() {
    int i = blockIdx.x * blockDim.x + threadIdx.x;
    if (i < NN) g_deg[i] = 0;
}

__global__ void k_count(const int* __restrict__ ei) {
    int e4 = blockIdx.x * blockDim.x + threadIdx.x;
    if (e4 < EE / 4) {
        int4 d = ((const int4*)(ei + EE))[e4];
        atomicAdd(&g_deg[d.x], 1);
        atomicAdd(&g_deg[d.y], 1);
        atomicAdd(&g_deg[d.z], 1);
        atomicAdd(&g_deg[d.w], 1);
    }
}

__global__ void k_scanA() {
    __shared__ int s[256];
    int t = threadIdx.x, b = blockIdx.x;
    int i = b * 256 + t;
    int v = (i < NN) ? g_deg[i] : 0;
    s[t] = v;
    __syncthreads();
#pragma unroll
    for (int off = 1; off < 256; off <<= 1) {
        int u = s[t];
        int add = (t >= off) ? s[t - off] : 0;
        __syncthreads();
        s[t] = u + add;
        __syncthreads();
    }
    if (i < NN) g_rowptr[i] = s[t] - v;
    if (t == 255) g_bsum[b] = s[255];
}

__global__ void k_scanB() {
    __shared__ int s[256];
    int t = threadIdx.x;
    int v = (t < 196) ? g_bsum[t] : 0;
    s[t] = v;
    __syncthreads();
#pragma unroll
    for (int off = 1; off < 256; off <<= 1) {
        int u = s[t];
        int add = (t >= off) ? s[t - off] : 0;
        __syncthreads();
        s[t] = u + add;
        __syncthreads();
    }
    g_boff[t] = s[t] - v;
    if (t == 255) g_rowptr[NN] = s[255];
}

__global__ void k_scanC() {
    int i = blockIdx.x * blockDim.x + threadIdx.x;
    if (i < NN) {
        int r = g_rowptr[i] + g_boff[blockIdx.x];
        g_rowptr[i] = r;
        g_cursor[i] = r;
        g_dis[i] = rsqrtf((float)(g_deg[i] + 1));
    }
}

__global__ void k_scatter(const int* __restrict__ ei) {
    int e4 = blockIdx.x * blockDim.x + threadIdx.x;
    if (e4 < EE / 4) {
        int4 s = ((const int4*)ei)[e4];
        int4 d = ((const int4*)(ei + EE))[e4];
        int p0 = atomicAdd(&g_cursor[d.x], 1);
        int p1 = atomicAdd(&g_cursor[d.y], 1);
        int p2 = atomicAdd(&g_cursor[d.z], 1);
        int p3 = atomicAdd(&g_cursor[d.w], 1);
        g_csr[p0] = s.x;
        g_csr[p1] = s.y;
        g_csr[p2] = s.z;
        g_csr[p3] = s.w;
    }
}

// ---------------- pre-convert W = [W_gcn | W_ps] to n-major fp16 ----------------
__global__ void k_convB(const float* __restrict__ Wg, const float* __restrict__ Wps) {
    int t = blockIdx.x * blockDim.x + threadIdx.x;
    if (t >= 96 * KP2) return;
    int n = t / KP2, k = t - n * KP2;
    float v = 0.f;
    if (k < KDIM) v = (n < 64) ? Wg[k * 64 + n] : Wps[k * 32 + (n - 64)];
    g_Wh[t] = __float2half_rn(v);
}

// ---------------- in-place scale: g_yh[row] *= dis[row] (after GEMM + scanC) ----
__global__ void k_scale() {
    int t = blockIdx.x * blockDim.x + threadIdx.x;     // one uint4 = 8 halves
    if (t >= NN * 8) return;
    int row = t >> 3;
    float dn = g_dis[row];
    uint4 u = ((const uint4*)g_yh)[t];
    __half2* h2 = (__half2*)&u;
#pragma unroll
    for (int i = 0; i < 4; i++) {
        float2 f = __half22float2(h2[i]);
        h2[i] = __floats2half2_rn(f.x * dn, f.y * dn);
    }
    ((uint4*)g_yh)[t] = u;
}

// ---------------- tensor GEMM: x @ [W_gcn | W_ps], single-term fp16 ----------------
#define ASTRIDE 40
#define STG_AH 0
#define STG_B  10240
#define STG_SZ 17920
#define SMEM_GEMM (2 * STG_SZ)

#define MMA_F16(D, A0, A1, A2, A3, B0, B1)                                   \
    asm volatile(                                                            \
        "mma.sync.aligned.m16n8k16.row.col.f32.f16.f16.f32 "                 \
        "{%0,%1,%2,%3}, {%4,%5,%6,%7}, {%8,%9}, {%0,%1,%2,%3};\n"            \
        : "+f"((D)[0]), "+f"((D)[1]), "+f"((D)[2]), "+f"((D)[3])             \
        : "r"(A0), "r"(A1), "r"(A2), "r"(A3), "r"(B0), "r"(B1))

#define LDSM_X4(R0, R1, R2, R3, ADDR)                                        \
    asm volatile("ldmatrix.sync.aligned.m8n8.x4.shared.b16 {%0,%1,%2,%3}, [%4];" \
        : "=r"(R0), "=r"(R1), "=r"(R2), "=r"(R3) : "r"(ADDR))

#define LDSM_X2(R0, R1, ADDR)                                                \
    asm volatile("ldmatrix.sync.aligned.m8n8.x2.shared.b16 {%0,%1}, [%2];"   \
        : "=r"(R0), "=r"(R1) : "r"(ADDR))

__global__ __launch_bounds__(256, 2) void k_gemm(
    const float* __restrict__ x,
    const float* __restrict__ bps,
    float* __restrict__ zsem)
{
    extern __shared__ char sm[];
    const uint32_t smb = (uint32_t)__cvta_generic_to_shared(sm);
    const int tid    = threadIdx.x;
    const int lane   = tid & 31;
    const int wid    = tid >> 5;
    const int warp_m = wid >> 2;
    const int warp_n = wid & 3;
    const int row0   = blockIdx.x * 128;

    float acc[4][3][4];
#pragma unroll
    for (int i = 0; i < 4; i++)
#pragma unroll
        for (int j = 0; j < 3; j++)
#pragma unroll
            for (int q = 0; q < 4; q++) acc[i][j][q] = 0.f;

    float fA[16];
    uint4 fB[2];
    const int ar = tid >> 4;          // base row (0..15), +16 per task step
    const int ac = (tid & 15) * 2;    // k-pair column

    const int a_loff = (warp_m * 64 + (lane & 15)) * ASTRIDE + (lane >> 4) * 8;
    const int b_loff = (warp_n * 24 + (lane & 7)) * ASTRIDE + ((lane >> 3) & 1) * 8;

    auto ldg_tile = [&](int j) {
        const int kt = j * 32;
#pragma unroll
        for (int i = 0; i < 8; i++) {
            int r = i * 16 + ar;
            int grow = row0 + r, gk = kt + ac;
            float f0 = 0.f, f1 = 0.f;
            if (grow < NN) {
                const float* xp = x + (size_t)grow * KDIM + gk;
                if (gk < KDIM)     f0 = __ldg(xp);
                if (gk + 1 < KDIM) f1 = __ldg(xp + 1);
            }
            fA[2 * i] = f0; fA[2 * i + 1] = f1;
        }
        {
            int n = tid >> 2, q = tid & 3;
            fB[0] = *(const uint4*)((const char*)g_Wh + ((size_t)n * KP2 + kt) * 2 + q * 16);
            if (tid < 128) {
                int t1 = tid + 256;
                int n1 = t1 >> 2, q1 = t1 & 3;
                fB[1] = *(const uint4*)((const char*)g_Wh + ((size_t)n1 * KP2 + kt) * 2 + q1 * 16);
            }
        }
    };

    auto sts_tile = [&](int buf) {
        char* base = sm + buf * STG_SZ;
        __half* Ah = (__half*)(base + STG_AH);
        __half* Bs = (__half*)(base + STG_B);
#pragma unroll
        for (int i = 0; i < 8; i++) {
            int r = i * 16 + ar;
            __half2 h2 = __floats2half2_rn(fA[2 * i], fA[2 * i + 1]);
            *(uint32_t*)&Ah[r * ASTRIDE + ac] = *(uint32_t*)&h2;
        }
        {
            int n = tid >> 2, q = tid & 3;
            *(uint4*)&Bs[n * ASTRIDE + q * 8] = fB[0];
            if (tid < 128) {
                int t1 = tid + 256;
                int n1 = t1 >> 2, q1 = t1 & 3;
                *(uint4*)&Bs[n1 * ASTRIDE + q1 * 8] = fB[1];
            }
        }
    };

    auto compute = [&](int buf) {
        uint32_t ahb = smb + buf * STG_SZ + STG_AH + a_loff * 2;
        uint32_t bsb = smb + buf * STG_SZ + STG_B  + b_loff * 2;
#pragma unroll
        for (int ks = 0; ks < 32; ks += 16) {
            uint32_t bb[3][2];
#pragma unroll
            for (int nt = 0; nt < 3; nt++)
                LDSM_X2(bb[nt][0], bb[nt][1], bsb + (nt * 8 * ASTRIDE + ks) * 2);
#pragma unroll
            for (int mt = 0; mt < 4; mt++) {
                uint32_t a0, a1, a2, a3;
                LDSM_X4(a0, a1, a2, a3, ahb + (mt * 16 * ASTRIDE + ks) * 2);
#pragma unroll
                for (int nt = 0; nt < 3; nt++)
                    MMA_F16(acc[mt][nt], a0, a1, a2, a3, bb[nt][0], bb[nt][1]);
            }
        }
    };

    ldg_tile(0);
    sts_tile(0);
    __syncthreads();
    for (int j = 1; j < NITER; j++) {
        ldg_tile(j);
        compute((j - 1) & 1);
        sts_tile(j & 1);
        __syncthreads();
    }
    compute((NITER - 1) & 1);

    // epilogue: y raw -> fp16 pairs (scaled later by k_scale), zsem = +bps (fp32)
#pragma unroll
    for (int mt = 0; mt < 4; mt++) {
#pragma unroll
        for (int nt = 0; nt < 3; nt++) {
            int row = row0 + warp_m * 64 + mt * 16 + (lane >> 2);
            int col = warp_n * 24 + nt * 8 + (lane & 3) * 2;
            const float* d = acc[mt][nt];
#pragma unroll
            for (int half = 0; half < 2; half++) {
                int rr = row + half * 8;
                if (rr >= NN) continue;
                float v0 = d[half * 2], v1 = d[half * 2 + 1];
                if (col < 64) {
                    __half2 h2 = __floats2half2_rn(v0, v1);
                    *(uint32_t*)&g_yh[(size_t)rr * 64 + col] = *(uint32_t*)&h2;
                } else {
                    zsem[(size_t)rr * 32 + (col - 64)]     = v0 + bps[col - 64];
                    zsem[(size_t)rr * 32 + (col - 64) + 1] = v1 + bps[col - 63];
                }
            }
        }
    }
}

// ---------------- gather-aggregate + tail fusion (1 warp/node, pre-scaled y) ----
__global__ __launch_bounds__(256) void k_agg(
    const float* __restrict__ bg,
    const float* __restrict__ Wpt, const float* __restrict__ bpt,
    const float* __restrict__ Wcls, const float* __restrict__ bcls,
    const float* __restrict__ zsem,
    float* __restrict__ logits, float* __restrict__ anom, float* __restrict__ ztopo)
{
    __shared__ float sWpt[64 * 32];
    __shared__ float sWcls[32 * 7];
    __shared__ float sbpt[32];
    __shared__ float sbcls[8];
    __shared__ float sbg[64];
    __shared__ float sh[8][64];
    __shared__ float sz[8][32];

    int tid = threadIdx.x;
    for (int i = tid; i < 64 * 32; i += 256) sWpt[i] = Wpt[i];
    for (int i = tid; i < 32 * 7;  i += 256) sWcls[i] = Wcls[i];
    if (tid < 32) sbpt[tid] = bpt[tid];
    if (tid < 7)  sbcls[tid] = bcls[tid];
    if (tid < 64) sbg[tid] = bg[tid];
    __syncthreads();

    int warp = tid >> 5, lane = tid & 31;
    int node = blockIdx.x * 8 + warp;
    if (node >= NN) return;

    const uint2* y2 = (const uint2*)g_yh;           // 16 uint2 per row (4 halves each)
    const int half = lane >> 4;                     // 0: even nbrs, 1: odd nbrs
    const int q = lane & 15;                        // col group [4q,4q+4)
    const float dn = g_dis[node];

    auto cvt = [](uint2 u) {
        const __half2* h = (const __half2*)&u;
        float2 a = __half22float2(h[0]);
        float2 b = __half22float2(h[1]);
        return make_float4(a.x, a.y, b.x, b.y);
    };

    float4 acc = make_float4(0.f, 0.f, 0.f, 0.f);
    if (half == 0) acc = cvt(y2[(size_t)node * 16 + q]);   // self loop (pre-scaled)

    int p = g_rowptr[node], end = g_rowptr[node + 1];
    for (; p + 8 <= end; p += 8) {
        int s0 = g_csr[p + half],     s1 = g_csr[p + 2 + half];
        int s2 = g_csr[p + 4 + half], s3 = g_csr[p + 6 + half];
        float4 v0 = cvt(y2[(size_t)s0 * 16 + q]);
        float4 v1 = cvt(y2[(size_t)s1 * 16 + q]);
        float4 v2 = cvt(y2[(size_t)s2 * 16 + q]);
        float4 v3 = cvt(y2[(size_t)s3 * 16 + q]);
        acc.x += (v0.x + v1.x) + (v2.x + v3.x);
        acc.y += (v0.y + v1.y) + (v2.y + v3.y);
        acc.z += (v0.z + v1.z) + (v2.z + v3.z);
        acc.w += (v0.w + v1.w) + (v2.w + v3.w);
    }
    for (; p + 2 <= end; p += 2) {
        int s = g_csr[p + half];
        float4 v = cvt(y2[(size_t)s * 16 + q]);
        acc.x += v.x; acc.y += v.y; acc.z += v.z; acc.w += v.w;
    }
    if (p < end && half == 0) {
        int s = g_csr[p];
        float4 v = cvt(y2[(size_t)s * 16 + q]);
        acc.x += v.x; acc.y += v.y; acc.z += v.z; acc.w += v.w;
    }
    // combine even/odd halves
    acc.x += __shfl_xor_sync(0xffffffffu, acc.x, 16);
    acc.y += __shfl_xor_sync(0xffffffffu, acc.y, 16);
    acc.z += __shfl_xor_sync(0xffffffffu, acc.z, 16);
    acc.w += __shfl_xor_sync(0xffffffffu, acc.w, 16);

    if (half == 0) {
        sh[warp][4 * q + 0] = fmaxf(fmaf(dn, acc.x, sbg[4 * q + 0]), 0.f);
        sh[warp][4 * q + 1] = fmaxf(fmaf(dn, acc.y, sbg[4 * q + 1]), 0.f);
        sh[warp][4 * q + 2] = fmaxf(fmaf(dn, acc.z, sbg[4 * q + 2]), 0.f);
        sh[warp][4 * q + 3] = fmaxf(fmaf(dn, acc.w, sbg[4 * q + 3]), 0.f);
    }
    __syncwarp();

    float z = sbpt[lane];
#pragma unroll
    for (int k = 0; k < 64; k++)
        z = fmaf(sh[warp][k], sWpt[k * 32 + lane], z);
    ztopo[(size_t)node * 32 + lane] = z;
    sz[warp][lane] = z;

    float d = z - zsem[(size_t)node * 32 + lane];
    float ss = d * d;
#pragma unroll
    for (int off = 16; off; off >>= 1) ss += __shfl_xor_sync(0xffffffffu, ss, off);
    if (lane == 0) anom[node] = sqrtf(ss);
    __syncwarp();

    if (lane < NC) {
        float lg = sbcls[lane];
#pragma unroll
        for (int l = 0; l < 32; l++)
            lg = fmaf(sz[warp][l], sWcls[l * 7 + lane], lg);
        logits[(size_t)node * 7 + lane] = lg;
    }
}

// ---------------- launch: fork GEMM onto side stream; gemm submitted 4th ------
extern "C" void kernel_launch(void* const* d_in, const int* in_sizes, int n_in,
                              void* d_out, int out_size)
{
    const float* x    = (const float*)d_in[0];
    const int*   ei   = (const int*)  d_in[1];
    const float* Wg   = (const float*)d_in[2];
    const float* bg   = (const float*)d_in[3];
    const float* Wpt  = (const float*)d_in[4];
    const float* bpt  = (const float*)d_in[5];
    const float* Wps  = (const float*)d_in[6];
    const float* bps  = (const float*)d_in[7];
    const float* Wcls = (const float*)d_in[8];
    const float* bcls = (const float*)d_in[9];

    float* out    = (float*)d_out;               // [logits | anomaly | z_topo | z_sem]
    float* logits = out;
    float* anom   = out + (size_t)NN * NC;
    float* ztopo  = anom + NN;
    float* zsem   = ztopo + (size_t)NN * 32;

    cudaFuncSetAttribute(k_gemm, cudaFuncAttributeMaxDynamicSharedMemorySize, SMEM_GEMM);

    // fork at graph entry; s2 runs convB + GEMM (no CSR dependency)
    cudaEventRecord(g_ev0, 0);
    cudaStreamWaitEvent(g_s2, g_ev0, 0);

    // main: first two CSR kernels (submissions 1-2)
    k_zero_deg<<<(NN + 255) / 256, 256>>>();
    k_count  <<<(EE / 4 + 255) / 256, 256>>>(ei);

    // side stream (submissions 3-4 — puts k_gemm in ncu's capture slot)
    k_convB<<<(96 * KP2 + 255) / 256, 256, 0, g_s2>>>(Wg, Wps);
    k_gemm <<<(NN + 127) / 128, 256, SMEM_GEMM, g_s2>>>(x, bps, zsem);
    cudaEventRecord(g_ev1, g_s2);

    // main: rest of CSR chain
    k_scanA  <<<196, 256>>>();
    k_scanB  <<<1, 256>>>();
    k_scanC  <<<196, 256>>>();
    k_scatter<<<(EE / 4 + 255) / 256, 256>>>(ei);

    // join, scale y by dis, then aggregate + tail
    cudaStreamWaitEvent(0, g_ev1, 0);
    k_scale<<<(NN * 8 + 255) / 256, 256>>>();
    k_agg<<<(NN + 7) / 8, 256>>>(bg, Wpt, bpt, Wcls, bcls, zsem, logits, anom, ztopo);
}

// round 12
// speedup vs baseline: 1.0743x; 1.0743x over previous
#include <cuda_runtime.h>
#include <cuda_fp16.h>
#include <cstdint>
#include <math.h>

#define NN   50000
#define EE   1600000
#define KDIM 1433
#define KP2  1440        // 45 * 32
#define NC   7
#define NITER 45

// ---------------- scratch (device globals; no allocs allowed) ----------------
__device__ __half g_yh[(size_t)NN * 64]; // raw x @ W_gcn  [N,64] fp16
__device__ int   g_deg[NN];
__device__ float g_dis[NN];
__device__ int   g_rowptr[NN + 1];
__device__ int   g_cursor[NN];
__device__ int   g_csr[EE];
__device__ int   g_bsum[256];
__device__ int   g_boff[256];
__device__ __half g_Wh[96 * KP2];        // n-major fp16 of [Wg|Wps]

// ---------------- stream/event fork (created once at load; host objects) ------
static cudaStream_t g_s2;
static cudaEvent_t  g_ev0, g_ev1;
namespace {
struct _StrInit {
    _StrInit() {
        cudaStreamCreateWithFlags(&g_s2, cudaStreamNonBlocking);
        cudaEventCreateWithFlags(&g_ev0, cudaEventDisableTiming);
        cudaEventCreateWithFlags(&g_ev1, cudaEventDisableTiming);
    }
};
_StrInit _str_init;
}

// ---------------- degree / CSR build ----------------
__global__ void k_zero_deg() {
    int i = blockIdx.x * blockDim.x + threadIdx.x;
    if (i < NN) g_deg[i] = 0;
}

__global__ void k_count(const int* __restrict__ ei) {
    int e4 = blockIdx.x * blockDim.x + threadIdx.x;
    if (e4 < EE / 4) {
        int4 d = ((const int4*)(ei + EE))[e4];
        atomicAdd(&g_deg[d.x], 1);
        atomicAdd(&g_deg[d.y], 1);
        atomicAdd(&g_deg[d.z], 1);
        atomicAdd(&g_deg[d.w], 1);
    }
}

__global__ void k_scanA() {
    __shared__ int s[256];
    int t = threadIdx.x, b = blockIdx.x;
    int i = b * 256 + t;
    int v = (i < NN) ? g_deg[i] : 0;
    s[t] = v;
    __syncthreads();
#pragma unroll
    for (int off = 1; off < 256; off <<= 1) {
        int u = s[t];
        int add = (t >= off) ? s[t - off] : 0;
        __syncthreads();
        s[t] = u + add;
        __syncthreads();
    }
    if (i < NN) g_rowptr[i] = s[t] - v;
    if (t == 255) g_bsum[b] = s[255];
}

__global__ void k_scanB() {
    __shared__ int s[256];
    int t = threadIdx.x;
    int v = (t < 196) ? g_bsum[t] : 0;
    s[t] = v;
    __syncthreads();
#pragma unroll
    for (int off = 1; off < 256; off <<= 1) {
        int u = s[t];
        int add = (t >= off) ? s[t - off] : 0;
        __syncthreads();
        s[t] = u + add;
        __syncthreads();
    }
    g_boff[t] = s[t] - v;
    if (t == 255) g_rowptr[NN] = s[255];
}

__global__ void k_scanC() {
    int i = blockIdx.x * blockDim.x + threadIdx.x;
    if (i < NN) {
        int r = g_rowptr[i] + g_boff[blockIdx.x];
        g_rowptr[i] = r;
        g_cursor[i] = r;
        g_dis[i] = rsqrtf((float)(g_deg[i] + 1));
    }
}

__global__ void k_scatter(const int* __restrict__ ei) {
    int e4 = blockIdx.x * blockDim.x + threadIdx.x;
    if (e4 < EE / 4) {
        int4 s = ((const int4*)ei)[e4];
        int4 d = ((const int4*)(ei + EE))[e4];
        int p0 = atomicAdd(&g_cursor[d.x], 1);
        int p1 = atomicAdd(&g_cursor[d.y], 1);
        int p2 = atomicAdd(&g_cursor[d.z], 1);
        int p3 = atomicAdd(&g_cursor[d.w], 1);
        g_csr[p0] = s.x;
        g_csr[p1] = s.y;
        g_csr[p2] = s.z;
        g_csr[p3] = s.w;
    }
}

// ---------------- pre-convert W = [W_gcn | W_ps] to n-major fp16 ----------------
__global__ void k_convB(const float* __restrict__ Wg, const float* __restrict__ Wps) {
    int t = blockIdx.x * blockDim.x + threadIdx.x;
    if (t >= 96 * KP2) return;
    int n = t / KP2, k = t - n * KP2;
    float v = 0.f;
    if (k < KDIM) v = (n < 64) ? Wg[k * 64 + n] : Wps[k * 32 + (n - 64)];
    g_Wh[t] = __float2half_rn(v);
}

// ---------------- tensor GEMM: x @ [W_gcn | W_ps], single-term fp16 ----------------
// Block tile 64 x 96, k-tile 32, 8 warps (each 32x24), 3 blocks/SM target.
#define ASTRIDE 40
#define STG_AH 0
#define STG_B  5120
#define STG_SZ 12800
#define SMEM_GEMM (2 * STG_SZ)

#define MMA_F16(D, A0, A1, A2, A3, B0, B1)                                   \
    asm volatile(                                                            \
        "mma.sync.aligned.m16n8k16.row.col.f32.f16.f16.f32 "                 \
        "{%0,%1,%2,%3}, {%4,%5,%6,%7}, {%8,%9}, {%0,%1,%2,%3};\n"            \
        : "+f"((D)[0]), "+f"((D)[1]), "+f"((D)[2]), "+f"((D)[3])             \
        : "r"(A0), "r"(A1), "r"(A2), "r"(A3), "r"(B0), "r"(B1))

#define LDSM_X4(R0, R1, R2, R3, ADDR)                                        \
    asm volatile("ldmatrix.sync.aligned.m8n8.x4.shared.b16 {%0,%1,%2,%3}, [%4];" \
        : "=r"(R0), "=r"(R1), "=r"(R2), "=r"(R3) : "r"(ADDR))

#define LDSM_X2(R0, R1, ADDR)                                                \
    asm volatile("ldmatrix.sync.aligned.m8n8.x2.shared.b16 {%0,%1}, [%2];"   \
        : "=r"(R0), "=r"(R1) : "r"(ADDR))

__global__ __launch_bounds__(256, 3) void k_gemm(
    const float* __restrict__ x,
    const float* __restrict__ bps,
    float* __restrict__ zsem)
{
    extern __shared__ char sm[];
    const uint32_t smb = (uint32_t)__cvta_generic_to_shared(sm);
    const int tid    = threadIdx.x;
    const int lane   = tid & 31;
    const int wid    = tid >> 5;
    const int warp_m = wid >> 2;      // 0..1  (32 rows)
    const int warp_n = wid & 3;       // 0..3  (24 cols)
    const int row0   = blockIdx.x * 64;

    float acc[2][3][4];
#pragma unroll
    for (int i = 0; i < 2; i++)
#pragma unroll
        for (int j = 0; j < 3; j++)
#pragma unroll
            for (int q = 0; q < 4; q++) acc[i][j][q] = 0.f;

    float fA[8];
    uint4 fB[2];
    const int ar = tid >> 4;          // base row (0..15), +16 per task step
    const int ac = (tid & 15) * 2;    // k-pair column

    const int a_loff = (warp_m * 32 + (lane & 15)) * ASTRIDE + (lane >> 4) * 8;
    const int b_loff = (warp_n * 24 + (lane & 7)) * ASTRIDE + ((lane >> 3) & 1) * 8;

    auto ldg_tile = [&](int j) {
        const int kt = j * 32;
#pragma unroll
        for (int i = 0; i < 4; i++) {
            int r = i * 16 + ar;
            int grow = row0 + r, gk = kt + ac;
            float f0 = 0.f, f1 = 0.f;
            if (grow < NN) {
                const float* xp = x + (size_t)grow * KDIM + gk;
                if (gk < KDIM)     f0 = __ldg(xp);
                if (gk + 1 < KDIM) f1 = __ldg(xp + 1);
            }
            fA[2 * i] = f0; fA[2 * i + 1] = f1;
        }
        {
            int n = tid >> 2, q = tid & 3;
            fB[0] = *(const uint4*)((const char*)g_Wh + ((size_t)n * KP2 + kt) * 2 + q * 16);
            if (tid < 128) {
                int t1 = tid + 256;
                int n1 = t1 >> 2, q1 = t1 & 3;
                fB[1] = *(const uint4*)((const char*)g_Wh + ((size_t)n1 * KP2 + kt) * 2 + q1 * 16);
            }
        }
    };

    auto sts_tile = [&](int buf) {
        char* base = sm + buf * STG_SZ;
        __half* Ah = (__half*)(base + STG_AH);
        __half* Bs = (__half*)(base + STG_B);
#pragma unroll
        for (int i = 0; i < 4; i++) {
            int r = i * 16 + ar;
            __half2 h2 = __floats2half2_rn(fA[2 * i], fA[2 * i + 1]);
            *(uint32_t*)&Ah[r * ASTRIDE + ac] = *(uint32_t*)&h2;
        }
        {
            int n = tid >> 2, q = tid & 3;
            *(uint4*)&Bs[n * ASTRIDE + q * 8] = fB[0];
            if (tid < 128) {
                int t1 = tid + 256;
                int n1 = t1 >> 2, q1 = t1 & 3;
                *(uint4*)&Bs[n1 * ASTRIDE + q1 * 8] = fB[1];
            }
        }
    };

    auto compute = [&](int buf) {
        uint32_t ahb = smb + buf * STG_SZ + STG_AH + a_loff * 2;
        uint32_t bsb = smb + buf * STG_SZ + STG_B  + b_loff * 2;
#pragma unroll
        for (int ks = 0; ks < 32; ks += 16) {
            uint32_t bb[3][2];
#pragma unroll
            for (int nt = 0; nt < 3; nt++)
                LDSM_X2(bb[nt][0], bb[nt][1], bsb + (nt * 8 * ASTRIDE + ks) * 2);
#pragma unroll
            for (int mt = 0; mt < 2; mt++) {
                uint32_t a0, a1, a2, a3;
                LDSM_X4(a0, a1, a2, a3, ahb + (mt * 16 * ASTRIDE + ks) * 2);
#pragma unroll
                for (int nt = 0; nt < 3; nt++)
                    MMA_F16(acc[mt][nt], a0, a1, a2, a3, bb[nt][0], bb[nt][1]);
            }
        }
    };

    ldg_tile(0);
    sts_tile(0);
    __syncthreads();
    for (int j = 1; j < NITER; j++) {
        ldg_tile(j);
        compute((j - 1) & 1);
        sts_tile(j & 1);
        __syncthreads();
    }
    compute((NITER - 1) & 1);

    // epilogue: y raw -> fp16 pairs, zsem = +bps (fp32)
#pragma unroll
    for (int mt = 0; mt < 2; mt++) {
#pragma unroll
        for (int nt = 0; nt < 3; nt++) {
            int row = row0 + warp_m * 32 + mt * 16 + (lane >> 2);
            int col = warp_n * 24 + nt * 8 + (lane & 3) * 2;
            const float* d = acc[mt][nt];
#pragma unroll
            for (int half = 0; half < 2; half++) {
                int rr = row + half * 8;
                if (rr >= NN) continue;
                float v0 = d[half * 2], v1 = d[half * 2 + 1];
                if (col < 64) {
                    __half2 h2 = __floats2half2_rn(v0, v1);
                    *(uint32_t*)&g_yh[(size_t)rr * 64 + col] = *(uint32_t*)&h2;
                } else {
                    zsem[(size_t)rr * 32 + (col - 64)]     = v0 + bps[col - 64];
                    zsem[(size_t)rr * 32 + (col - 64) + 1] = v1 + bps[col - 63];
                }
            }
        }
    }
}

// ---------------- gather-aggregate + tail fusion (1 warp/node, dis-weighted) ----
__global__ __launch_bounds__(256) void k_agg(
    const float* __restrict__ bg,
    const float* __restrict__ Wpt, const float* __restrict__ bpt,
    const float* __restrict__ Wcls, const float* __restrict__ bcls,
    const float* __restrict__ zsem,
    float* __restrict__ logits, float* __restrict__ anom, float* __restrict__ ztopo)
{
    __shared__ float sWpt[64 * 32];
    __shared__ float sWcls[32 * 7];
    __shared__ float sbpt[32];
    __shared__ float sbcls[8];
    __shared__ float sbg[64];
    __shared__ float sh[8][64];
    __shared__ float sz[8][32];

    int tid = threadIdx.x;
    for (int i = tid; i < 64 * 32; i += 256) sWpt[i] = Wpt[i];
    for (int i = tid; i < 32 * 7;  i += 256) sWcls[i] = Wcls[i];
    if (tid < 32) sbpt[tid] = bpt[tid];
    if (tid < 7)  sbcls[tid] = bcls[tid];
    if (tid < 64) sbg[tid] = bg[tid];
    __syncthreads();

    int warp = tid >> 5, lane = tid & 31;
    int node = blockIdx.x * 8 + warp;
    if (node >= NN) return;

    const uint2* y2 = (const uint2*)g_yh;           // 16 uint2 per row (4 halves each)
    const int half = lane >> 4;                     // 0: even nbrs, 1: odd nbrs
    const int q = lane & 15;                        // col group [4q,4q+4)
    const float dn = g_dis[node];

    auto cvt = [](uint2 u) {
        const __half2* h = (const __half2*)&u;
        float2 a = __half22float2(h[0]);
        float2 b = __half22float2(h[1]);
        return make_float4(a.x, a.y, b.x, b.y);
    };

    float4 acc = make_float4(0.f, 0.f, 0.f, 0.f);
    if (half == 0) {                                 // self loop: dis[d]*y[d]
        float4 v = cvt(y2[(size_t)node * 16 + q]);
        acc.x = dn * v.x; acc.y = dn * v.y; acc.z = dn * v.z; acc.w = dn * v.w;
    }

    int p = g_rowptr[node], end = g_rowptr[node + 1];
    for (; p + 8 <= end; p += 8) {
        int s0 = g_csr[p + half],     s1 = g_csr[p + 2 + half];
        int s2 = g_csr[p + 4 + half], s3 = g_csr[p + 6 + half];
        float d0 = g_dis[s0], d1 = g_dis[s1], d2 = g_dis[s2], d3 = g_dis[s3];
        float4 v0 = cvt(y2[(size_t)s0 * 16 + q]);
        float4 v1 = cvt(y2[(size_t)s1 * 16 + q]);
        float4 v2 = cvt(y2[(size_t)s2 * 16 + q]);
        float4 v3 = cvt(y2[(size_t)s3 * 16 + q]);
        acc.x = fmaf(d0, v0.x, fmaf(d1, v1.x, fmaf(d2, v2.x, fmaf(d3, v3.x, acc.x))));
        acc.y = fmaf(d0, v0.y, fmaf(d1, v1.y, fmaf(d2, v2.y, fmaf(d3, v3.y, acc.y))));
        acc.z = fmaf(d0, v0.z, fmaf(d1, v1.z, fmaf(d2, v2.z, fmaf(d3, v3.z, acc.z))));
        acc.w = fmaf(d0, v0.w, fmaf(d1, v1.w, fmaf(d2, v2.w, fmaf(d3, v3.w, acc.w))));
    }
    for (; p + 2 <= end; p += 2) {
        int s = g_csr[p + half];
        float ds = g_dis[s];
        float4 v = cvt(y2[(size_t)s * 16 + q]);
        acc.x = fmaf(ds, v.x, acc.x); acc.y = fmaf(ds, v.y, acc.y);
        acc.z = fmaf(ds, v.z, acc.z); acc.w = fmaf(ds, v.w, acc.w);
    }
    if (p < end && half == 0) {
        int s = g_csr[p];
        float ds = g_dis[s];
        float4 v = cvt(y2[(size_t)s * 16 + q]);
        acc.x = fmaf(ds, v.x, acc.x); acc.y = fmaf(ds, v.y, acc.y);
        acc.z = fmaf(ds, v.z, acc.z); acc.w = fmaf(ds, v.w, acc.w);
    }
    // combine even/odd halves
    acc.x += __shfl_xor_sync(0xffffffffu, acc.x, 16);
    acc.y += __shfl_xor_sync(0xffffffffu, acc.y, 16);
    acc.z += __shfl_xor_sync(0xffffffffu, acc.z, 16);
    acc.w += __shfl_xor_sync(0xffffffffu, acc.w, 16);

    if (half == 0) {
        sh[warp][4 * q + 0] = fmaxf(fmaf(dn, acc.x, sbg[4 * q + 0]), 0.f);
        sh[warp][4 * q + 1] = fmaxf(fmaf(dn, acc.y, sbg[4 * q + 1]), 0.f);
        sh[warp][4 * q + 2] = fmaxf(fmaf(dn, acc.z, sbg[4 * q + 2]), 0.f);
        sh[warp][4 * q + 3] = fmaxf(fmaf(dn, acc.w, sbg[4 * q + 3]), 0.f);
    }
    __syncwarp();

    float z = sbpt[lane];
#pragma unroll
    for (int k = 0; k < 64; k++)
        z = fmaf(sh[warp][k], sWpt[k * 32 + lane], z);
    ztopo[(size_t)node * 32 + lane] = z;
    sz[warp][lane] = z;

    float d = z - zsem[(size_t)node * 32 + lane];
    float ss = d * d;
#pragma unroll
    for (int off = 16; off; off >>= 1) ss += __shfl_xor_sync(0xffffffffu, ss, off);
    if (lane == 0) anom[node] = sqrtf(ss);
    __syncwarp();

    if (lane < NC) {
        float lg = sbcls[lane];
#pragma unroll
        for (int l = 0; l < 32; l++)
            lg = fmaf(sz[warp][l], sWcls[l * 7 + lane], lg);
        logits[(size_t)node * 7 + lane] = lg;
    }
}

// ---------------- launch: fork GEMM onto side stream; gemm submitted 4th ------
extern "C" void kernel_launch(void* const* d_in, const int* in_sizes, int n_in,
                              void* d_out, int out_size)
{
    const float* x    = (const float*)d_in[0];
    const int*   ei   = (const int*)  d_in[1];
    const float* Wg   = (const float*)d_in[2];
    const float* bg   = (const float*)d_in[3];
    const float* Wpt  = (const float*)d_in[4];
    const float* bpt  = (const float*)d_in[5];
    const float* Wps  = (const float*)d_in[6];
    const float* bps  = (const float*)d_in[7];
    const float* Wcls = (const float*)d_in[8];
    const float* bcls = (const float*)d_in[9];

    float* out    = (float*)d_out;               // [logits | anomaly | z_topo | z_sem]
    float* logits = out;
    float* anom   = out + (size_t)NN * NC;
    float* ztopo  = anom + NN;
    float* zsem   = ztopo + (size_t)NN * 32;

    cudaFuncSetAttribute(k_gemm, cudaFuncAttributeMaxDynamicSharedMemorySize, SMEM_GEMM);

    // fork at graph entry; s2 runs convB + GEMM (no CSR dependency)
    cudaEventRecord(g_ev0, 0);
    cudaStreamWaitEvent(g_s2, g_ev0, 0);

    // main: first two CSR kernels (submissions 1-2)
    k_zero_deg<<<(NN + 255) / 256, 256>>>();
    k_count  <<<(EE / 4 + 255) / 256, 256>>>(ei);

    // side stream (submissions 3-4 — puts k_gemm in ncu's capture slot)
    k_convB<<<(96 * KP2 + 255) / 256, 256, 0, g_s2>>>(Wg, Wps);
    k_gemm <<<(NN + 63) / 64, 256, SMEM_GEMM, g_s2>>>(x, bps, zsem);
    cudaEventRecord(g_ev1, g_s2);

    // main: rest of CSR chain
    k_scanA  <<<196, 256>>>();
    k_scanB  <<<1, 256>>>();
    k_scanC  <<<196, 256>>>();
    k_scatter<<<(EE / 4 + 255) / 256, 256>>>(ei);

    // join, then aggregate + tail
    cudaStreamWaitEvent(0, g_ev1, 0);
    k_agg<<<(NN + 7) / 8, 256>>>(bg, Wpt, bpt, Wcls, bcls, zsem, logits, anom, ztopo);
}